// round 1
// baseline (speedup 1.0000x reference)
#include <cuda_runtime.h>
#include <math.h>

#define BB 256
#define CC 256
#define NN 196
#define MM (BB*NN)        // 50176
#define CMID 2048
#define EPSL 1e-5f

// ---------------- scratch (device globals; no allocation allowed) -------------
__device__ float g_t   [(size_t)MM*CC];        // [M, 256] tokens
__device__ float g_qkv [(size_t)MM*3*CC];      // [M, 768]
__device__ float g_attn[(size_t)MM*CC];        // [M, 256]
__device__ float g_t1  [(size_t)MM*CC];        // after repbn1
__device__ float g_h   [(size_t)MM*CMID];      // [M, 2048]
__device__ float g_t2  [(size_t)MM*CC];        // after repbn2

// ---------------- transpose x [B][C][N] -> t [B*N][C] ------------------------
__global__ void k_in_transpose(const float* __restrict__ x, float* __restrict__ t) {
    __shared__ float tile[32][33];
    int b = blockIdx.z;
    int n0 = blockIdx.x * 32, c0 = blockIdx.y * 32;
    int tx = threadIdx.x, ty = threadIdx.y;
    const float* xb = x + (size_t)b * CC * NN;
    #pragma unroll
    for (int j = 0; j < 32; j += 8) {
        int c = c0 + ty + j, n = n0 + tx;
        if (n < NN) tile[ty + j][tx] = xb[(size_t)c * NN + n];
    }
    __syncthreads();
    #pragma unroll
    for (int j = 0; j < 32; j += 8) {
        int n = n0 + ty + j, c = c0 + tx;
        if (n < NN) t[((size_t)b * NN + n) * CC + c] = tile[tx][ty + j];
    }
}

// ---------------- transpose t2 [B*N][C] -> out [B][C][N] ---------------------
__global__ void k_out_transpose(const float* __restrict__ t, float* __restrict__ out) {
    __shared__ float tile[32][33];
    int b = blockIdx.z;
    int c0 = blockIdx.x * 32, n0 = blockIdx.y * 32;
    int tx = threadIdx.x, ty = threadIdx.y;
    #pragma unroll
    for (int j = 0; j < 32; j += 8) {
        int n = n0 + ty + j, c = c0 + tx;
        if (n < NN) tile[ty + j][tx] = t[((size_t)b * NN + n) * CC + c];
    }
    __syncthreads();
    #pragma unroll
    for (int j = 0; j < 32; j += 8) {
        int c = c0 + ty + j, n = n0 + tx;
        if (n < NN) out[((size_t)b * CC + c) * NN + n] = tile[tx][ty + j];
    }
}

// ---------------- generic fp32 GEMM: out = A[M,K] @ W[K,N] + epilogue --------
// epi 0: +bias
// epi 1: +bias, y = res + v, repbn(y)  -> out
// epi 2: +bias, SpatialSILU: v * sigmoid((sa_w[b]*v + sa_b[b]) * v)
__global__ __launch_bounds__(256, 2)
void k_gemm(const float* __restrict__ A, const float* __restrict__ Bw,
            const float* __restrict__ bias, float* __restrict__ out,
            int M, int N, int K, int epi,
            const float* __restrict__ res,
            const float* __restrict__ gam, const float* __restrict__ bet,
            const float* __restrict__ rm,  const float* __restrict__ rv,
            const float* __restrict__ alpha,
            const float* __restrict__ saw, const float* __restrict__ sab)
{
    __shared__ float  As[16][132];
    __shared__ float4 Bs[16][32];
    int tid = threadIdx.x;
    int m0 = blockIdx.y * 128, n0 = blockIdx.x * 128;
    int ty = tid >> 4, tx = tid & 15;

    float acc[8][8];
    #pragma unroll
    for (int i = 0; i < 8; i++)
        #pragma unroll
        for (int j = 0; j < 8; j++) acc[i][j] = 0.f;

    int ar  = tid >> 2, ac4 = tid & 3;   // A tile: rows ar, ar+64; 4 floats at col4 ac4
    int bkr = tid >> 5, bc4 = tid & 31;  // B tile: rows bkr, bkr+8; float4 col bc4

    for (int k0 = 0; k0 < K; k0 += 16) {
        float4 a0 = *(const float4*)(A + (size_t)(m0 + ar     ) * K + k0 + ac4 * 4);
        float4 a1 = *(const float4*)(A + (size_t)(m0 + ar + 64) * K + k0 + ac4 * 4);
        float4 b0 = *(const float4*)(Bw + (size_t)(k0 + bkr    ) * N + n0 + bc4 * 4);
        float4 b1 = *(const float4*)(Bw + (size_t)(k0 + bkr + 8) * N + n0 + bc4 * 4);
        As[ac4*4+0][ar]    = a0.x; As[ac4*4+1][ar]    = a0.y;
        As[ac4*4+2][ar]    = a0.z; As[ac4*4+3][ar]    = a0.w;
        As[ac4*4+0][ar+64] = a1.x; As[ac4*4+1][ar+64] = a1.y;
        As[ac4*4+2][ar+64] = a1.z; As[ac4*4+3][ar+64] = a1.w;
        Bs[bkr][bc4]   = b0;
        Bs[bkr+8][bc4] = b1;
        __syncthreads();
        #pragma unroll
        for (int k = 0; k < 16; k++) {
            float arr[8];
            #pragma unroll
            for (int i = 0; i < 8; i++) arr[i] = As[k][ty * 8 + i];
            float4 bb0 = Bs[k][tx * 2], bb1 = Bs[k][tx * 2 + 1];
            float brr[8] = {bb0.x, bb0.y, bb0.z, bb0.w, bb1.x, bb1.y, bb1.z, bb1.w};
            #pragma unroll
            for (int i = 0; i < 8; i++)
                #pragma unroll
                for (int j = 0; j < 8; j++)
                    acc[i][j] += arr[i] * brr[j];
        }
        __syncthreads();
    }

    #pragma unroll
    for (int i = 0; i < 8; i++) {
        int m = m0 + ty * 8 + i;
        int bidx = m / NN;
        #pragma unroll
        for (int j = 0; j < 8; j++) {
            int n = n0 + tx * 8 + j;
            float v = acc[i][j] + bias[n];
            if (epi == 1) {
                float y = res[(size_t)m * N + n] + v;
                v = (y - rm[n]) * (gam[n] * rsqrtf(rv[n] + EPSL)) + bet[n] + alpha[0] * y;
            } else if (epi == 2) {
                float w = saw[bidx] * v + sab[bidx];
                v = v / (1.f + __expf(-w * v));
            }
            out[(size_t)m * N + n] = v;
        }
    }
}

// ---------------- attention: one block per (head, batch) ---------------------
__global__ void k_attn(const float* __restrict__ qkv, float* __restrict__ attnout) {
    extern __shared__ float sh[];
    float* Ks = sh;             // [196*32]
    float* Vs = sh + NN * 32;   // [196*32]
    int h = blockIdx.x, b = blockIdx.y;
    int tid = threadIdx.x;
    size_t base = (size_t)b * NN * 768;
    int koff = 256 + h * 32, voff = 512 + h * 32;
    for (int i = tid; i < NN * 32; i += 256) {
        int m = i >> 5, d = i & 31;
        Ks[i] = qkv[base + (size_t)m * 768 + koff + d];
        Vs[i] = qkv[base + (size_t)m * 768 + voff + d];
    }
    __syncthreads();
    if (tid < NN) {
        float q[32], o[32];
        const float* qp = qkv + base + (size_t)tid * 768 + h * 32;
        #pragma unroll
        for (int d = 0; d < 32; d++) { q[d] = qp[d] * 0.17677669529663687f; o[d] = 0.f; }
        float mx = -1e30f, l = 0.f;
        for (int m = 0; m < NN; m++) {
            const float* kr = Ks + m * 32;
            float s = 0.f;
            #pragma unroll
            for (int d = 0; d < 32; d++) s += q[d] * kr[d];
            float nm = fmaxf(mx, s);
            float f = __expf(mx - nm);
            float p = __expf(s - nm);
            l = l * f + p;
            const float* vr = Vs + m * 32;
            #pragma unroll
            for (int d = 0; d < 32; d++) o[d] = o[d] * f + p * vr[d];
            mx = nm;
        }
        float inv = 1.f / l;
        float* op = attnout + ((size_t)(b * NN + tid)) * CC + h * 32;
        #pragma unroll
        for (int d = 0; d < 32; d++) op[d] = o[d] * inv;
    }
}

// ---------------- launch ------------------------------------------------------
extern "C" void kernel_launch(void* const* d_in, const int* in_sizes, int n_in,
                              void* d_out, int out_size) {
    const float* x      = (const float*)d_in[0];
    const float* W_qkv  = (const float*)d_in[1];
    const float* b_qkv  = (const float*)d_in[2];
    const float* W_proj = (const float*)d_in[3];
    const float* b_proj = (const float*)d_in[4];
    const float* W1     = (const float*)d_in[5];
    const float* b1     = (const float*)d_in[6];
    const float* W2     = (const float*)d_in[7];
    const float* b2     = (const float*)d_in[8];
    const float* sa_w   = (const float*)d_in[9];
    const float* sa_b   = (const float*)d_in[10];
    const float* alpha1 = (const float*)d_in[11];
    const float* gamma1 = (const float*)d_in[12];
    const float* beta1  = (const float*)d_in[13];
    const float* rm1    = (const float*)d_in[14];
    const float* rv1    = (const float*)d_in[15];
    const float* alpha2 = (const float*)d_in[16];
    const float* gamma2 = (const float*)d_in[17];
    const float* beta2  = (const float*)d_in[18];
    const float* rm2    = (const float*)d_in[19];
    const float* rv2    = (const float*)d_in[20];
    float* out = (float*)d_out;

    float *t, *qkv, *attn, *t1, *hbuf, *t2;
    cudaGetSymbolAddress((void**)&t,    g_t);
    cudaGetSymbolAddress((void**)&qkv,  g_qkv);
    cudaGetSymbolAddress((void**)&attn, g_attn);
    cudaGetSymbolAddress((void**)&t1,   g_t1);
    cudaGetSymbolAddress((void**)&hbuf, g_h);
    cudaGetSymbolAddress((void**)&t2,   g_t2);

    cudaFuncSetAttribute(k_attn, cudaFuncAttributeMaxDynamicSharedMemorySize, 2 * NN * 32 * 4);

    dim3 tb(32, 8);
    // 1) x -> tokens
    k_in_transpose<<<dim3(7, 8, BB), tb>>>(x, t);
    // 2) QKV GEMM [50176,256]@[256,768]
    k_gemm<<<dim3(768 / 128, MM / 128), 256>>>(t, W_qkv, b_qkv, qkv, MM, 768, 256, 0,
        nullptr, nullptr, nullptr, nullptr, nullptr, nullptr, nullptr, nullptr);
    // 3) attention per (h, b)
    k_attn<<<dim3(8, BB), 256, 2 * NN * 32 * 4>>>(qkv, attn);
    // 4) proj + residual + repbn1
    k_gemm<<<dim3(256 / 128, MM / 128), 256>>>(attn, W_proj, b_proj, t1, MM, 256, 256, 1,
        t, gamma1, beta1, rm1, rv1, alpha1, nullptr, nullptr);
    // 5) FFN1 + SpatialSILU
    k_gemm<<<dim3(CMID / 128, MM / 128), 256>>>(t1, W1, b1, hbuf, MM, CMID, 256, 2,
        nullptr, nullptr, nullptr, nullptr, nullptr, nullptr, sa_w, sa_b);
    // 6) FFN2 + residual + repbn2
    k_gemm<<<dim3(256 / 128, MM / 128), 256>>>(hbuf, W2, b2, t2, MM, 256, CMID, 1,
        t1, gamma2, beta2, rm2, rv2, alpha2, nullptr, nullptr);
    // 7) tokens -> output layout
    k_out_transpose<<<dim3(8, 7, BB), tb>>>(t2, out);
}

// round 3
// speedup vs baseline: 1.6326x; 1.6326x over previous
#include <cuda_runtime.h>
#include <cstdint>
#include <math.h>

#define BB 256
#define CC 256
#define NN 196
#define MM (BB*NN)        // 50176
#define CMID 2048
#define EPSL 1e-5f

// tcgen05 PTX is only legal in the arch-specific ('a') compilation pass.
#if defined(__CUDA_ARCH_FEAT_SM103_ALL) || defined(__CUDA_ARCH_FEAT_SM100_ALL) || defined(__CUDA_ARCH_FEAT_SM101_ALL)
#define TC_OK 1
#else
#define TC_OK 0
#endif

// ---------------- scratch (device globals) -----------------------------------
__device__ float g_t   [(size_t)MM*CC];
__device__ float g_qkv [(size_t)MM*3*CC];
__device__ float g_attn[(size_t)MM*CC];
__device__ float g_t1  [(size_t)MM*CC];
__device__ float g_h   [(size_t)MM*CMID];
__device__ float g_t2  [(size_t)MM*CC];
__device__ float g_wqkvT[(size_t)3*CC*CC];   // [768,256]
__device__ float g_wprojT[(size_t)CC*CC];    // [256,256]
__device__ float g_w1T  [(size_t)CMID*CC];   // [2048,256]
__device__ float g_w2T  [(size_t)CC*CMID];   // [256,2048]

// ---------------- PTX helpers -------------------------------------------------
__device__ __forceinline__ uint32_t smem_u32(const void* p) {
    uint32_t a;
    asm("{ .reg .u64 t; cvta.to.shared.u64 t, %1; cvt.u32.u64 %0, t; }" : "=r"(a) : "l"(p));
    return a;
}

#define MBAR_INIT(addr, cnt) \
    asm volatile("mbarrier.init.shared.b64 [%0], %1;" :: "r"(addr), "r"(cnt) : "memory")

#define MBAR_WAIT(addr, parity) do {                                              \
    uint32_t _m = (addr); uint32_t _p = (parity); uint32_t _d;                    \
    asm volatile("{\n\t.reg .pred p;\n\t"                                         \
        "mbarrier.try_wait.parity.acquire.cta.shared::cta.b64 p, [%1], %2;\n\t"   \
        "selp.b32 %0, 1, 0, p;\n\t}" : "=r"(_d) : "r"(_m), "r"(_p) : "memory");   \
    if (!_d) {                                                                     \
        asm volatile("{\n\t.reg .pred P1;\n\t"                                     \
            "W_%=:\n\t"                                                            \
            "mbarrier.try_wait.parity.acquire.cta.shared::cta.b64 P1, [%0], %1, 0x989680;\n\t" \
            "@P1 bra.uni D_%=;\n\t"                                                \
            "bra.uni W_%=;\n\t"                                                    \
            "D_%=:\n\t}" :: "r"(_m), "r"(_p) : "memory");                          \
    } } while (0)

#if TC_OK
__device__ __forceinline__ void mma_tf32(uint32_t d, uint64_t ad, uint64_t bd,
                                         uint32_t idesc, bool acc) {
    uint32_t e = acc ? 1u : 0u;
    asm volatile(
        "{\n\t.reg .pred p;\n\tsetp.ne.u32 p, %5, 0;\n\t"
        "tcgen05.mma.cta_group::1.kind::tf32 [%0], %1, %2, %3, {%4, %4, %4, %4}, p;\n\t}"
        :: "r"(d), "l"(ad), "l"(bd), "r"(idesc), "r"(0u), "r"(e) : "memory");
}

#define LDTM_X32(r, addr)                                                         \
    asm volatile("tcgen05.ld.sync.aligned.32x32b.x32.b32 "                        \
        "{%0, %1, %2, %3, %4, %5, %6, %7, %8, %9, %10, %11, %12, %13, %14, %15, " \
        " %16, %17, %18, %19, %20, %21, %22, %23, %24, %25, %26, %27, %28, %29, %30, %31}, [%32];" \
        : "=r"((r)[0]), "=r"((r)[1]), "=r"((r)[2]), "=r"((r)[3]),                 \
          "=r"((r)[4]), "=r"((r)[5]), "=r"((r)[6]), "=r"((r)[7]),                 \
          "=r"((r)[8]), "=r"((r)[9]), "=r"((r)[10]), "=r"((r)[11]),               \
          "=r"((r)[12]), "=r"((r)[13]), "=r"((r)[14]), "=r"((r)[15]),             \
          "=r"((r)[16]), "=r"((r)[17]), "=r"((r)[18]), "=r"((r)[19]),             \
          "=r"((r)[20]), "=r"((r)[21]), "=r"((r)[22]), "=r"((r)[23]),             \
          "=r"((r)[24]), "=r"((r)[25]), "=r"((r)[26]), "=r"((r)[27]),             \
          "=r"((r)[28]), "=r"((r)[29]), "=r"((r)[30]), "=r"((r)[31])              \
        : "r"(addr))
#endif

static constexpr uint64_t DESC_BASE =
    (uint64_t(2) << 61) | (uint64_t(1) << 46) | (uint64_t(64) << 32) | (uint64_t(1) << 16);

// ---------------- transpose x [B][C][N] -> t [B*N][C] -------------------------
__global__ void k_in_transpose(const float* __restrict__ x, float* __restrict__ t) {
    __shared__ float tile[32][33];
    int b = blockIdx.z;
    int n0 = blockIdx.x * 32, c0 = blockIdx.y * 32;
    int tx = threadIdx.x, ty = threadIdx.y;
    const float* xb = x + (size_t)b * CC * NN;
    #pragma unroll
    for (int j = 0; j < 32; j += 8) {
        int c = c0 + ty + j, n = n0 + tx;
        if (n < NN) tile[ty + j][tx] = xb[(size_t)c * NN + n];
    }
    __syncthreads();
    #pragma unroll
    for (int j = 0; j < 32; j += 8) {
        int n = n0 + ty + j, c = c0 + tx;
        if (n < NN) t[((size_t)b * NN + n) * CC + c] = tile[tx][ty + j];
    }
}

// ---------------- transpose t2 [B*N][C] -> out [B][C][N] ----------------------
__global__ void k_out_transpose(const float* __restrict__ t, float* __restrict__ out) {
    __shared__ float tile[32][33];
    int b = blockIdx.z;
    int c0 = blockIdx.x * 32, n0 = blockIdx.y * 32;
    int tx = threadIdx.x, ty = threadIdx.y;
    #pragma unroll
    for (int j = 0; j < 32; j += 8) {
        int n = n0 + ty + j, c = c0 + tx;
        if (n < NN) tile[ty + j][tx] = t[((size_t)b * NN + n) * CC + c];
    }
    __syncthreads();
    #pragma unroll
    for (int j = 0; j < 32; j += 8) {
        int c = c0 + ty + j, n = n0 + tx;
        if (n < NN) out[((size_t)b * CC + c) * NN + n] = tile[tx][ty + j];
    }
}

// ---------------- weight transpose W[R,C] -> Wt[C,R] --------------------------
__global__ void k_wt(const float* __restrict__ W, float* __restrict__ Wt, int R, int C) {
    __shared__ float tile[32][33];
    int c0 = blockIdx.x * 32, r0 = blockIdx.y * 32;
    int tx = threadIdx.x, ty = threadIdx.y;
    #pragma unroll
    for (int j = 0; j < 32; j += 8)
        tile[ty + j][tx] = W[(size_t)(r0 + ty + j) * C + c0 + tx];
    __syncthreads();
    #pragma unroll
    for (int j = 0; j < 32; j += 8)
        Wt[(size_t)(c0 + ty + j) * R + r0 + tx] = tile[tx][ty + j];
}

// ---------------- tcgen05 tf32 GEMM: out[M,N] = A[M,K] @ Bt[N,K]^T + epilogue -
// epi 0: +bias
// epi 1: +bias, y = res + v, repbn(y)
// epi 2: +bias, SpatialSILU
__global__ __launch_bounds__(256)
void k_tgemm(const float* __restrict__ A, const float* __restrict__ Bt,
             const float* __restrict__ bias, float* __restrict__ out,
             int M, int N, int K, int epi,
             const float* __restrict__ res,
             const float* __restrict__ gam, const float* __restrict__ bet,
             const float* __restrict__ rm,  const float* __restrict__ rv,
             const float* __restrict__ alpha,
             const float* __restrict__ saw, const float* __restrict__ sab)
{
#if TC_OK
    extern __shared__ char smem_raw[];
    __shared__ uint64_t s_mbar[2];
    __shared__ uint32_t s_tmem;

    uint32_t sb_raw = smem_u32(smem_raw);
    uint32_t tbase = (sb_raw + 1023u) & ~1023u;      // 1KB-aligned tile base (smem addr)
    char* tptr = smem_raw + (tbase - sb_raw);        // generic ptr to same place

    int tid = threadIdx.x;
    int wid = tid >> 5, lid = tid & 31;
    int m0 = blockIdx.y * 128, n0 = blockIdx.x * 128;

    if (wid == 0)
        asm volatile("tcgen05.alloc.cta_group::1.sync.aligned.shared::cta.b32 [%0], %1;"
                     :: "r"(smem_u32(&s_tmem)), "r"(128) : "memory");
    if (tid == 0) {
        MBAR_INIT(smem_u32(&s_mbar[0]), 1);
        MBAR_INIT(smem_u32(&s_mbar[1]), 1);
    }
    __syncthreads();
    uint32_t tmem = s_tmem;
    if (wid == 0)
        asm volatile("tcgen05.relinquish_alloc_permit.cta_group::1.sync.aligned;");

    // idesc: D=f32, A=tf32, B=tf32, N=128, M=128
    const uint32_t IDESC = (1u << 4) | (2u << 7) | (2u << 10) | (16u << 17) | (8u << 24);
    const int KC = K >> 5;
    int ph0 = 0, ph1 = 0;

    for (int kc = 0; kc < KC; kc++) {
        int buf = kc & 1;
        uint32_t mb = smem_u32(&s_mbar[buf]);
        if (kc >= 2) {
            if (buf == 0) { MBAR_WAIT(mb, ph0); ph0 ^= 1; }
            else          { MBAR_WAIT(mb, ph1); ph1 ^= 1; }
        }
        char* tA = tptr + buf * 32768;
        char* tB = tA + 16384;
        const float* Ag = A + (size_t)m0 * K + kc * 32;
        const float* Bg = Bt + (size_t)n0 * K + kc * 32;
        #pragma unroll
        for (int i = 0; i < 4; i++) {
            int idx = tid + i * 256;
            int row = idx >> 3, c4 = idx & 7;
            float4 av = *(const float4*)(Ag + (size_t)row * K + c4 * 4);
            float4 bv = *(const float4*)(Bg + (size_t)row * K + c4 * 4);
            uint32_t bo = row * 128 + c4 * 16;
            uint32_t sw = bo ^ ((bo >> 3) & 0x70);
            *(float4*)(tA + sw) = av;
            *(float4*)(tB + sw) = bv;
        }
        asm volatile("fence.proxy.async.shared::cta;" ::: "memory");
        __syncthreads();
        if (tid == 0) {
            uint32_t sA = tbase + buf * 32768;
            uint32_t sB = sA + 16384;
            uint64_t ad = DESC_BASE | ((uint64_t)(sA >> 4) & 0x3FFF);
            uint64_t bd = DESC_BASE | ((uint64_t)(sB >> 4) & 0x3FFF);
            #pragma unroll
            for (int s = 0; s < 4; s++)
                mma_tf32(tmem, ad + s * 2, bd + s * 2, IDESC, (kc > 0) || (s > 0));
            asm volatile(
                "tcgen05.commit.cta_group::1.mbarrier::arrive::one.shared::cluster.b64 [%0];"
                :: "r"(mb) : "memory");
        }
    }

    // wait for the last chunk's mma
    {
        int lb = (KC - 1) & 1;
        uint32_t mb = smem_u32(&s_mbar[lb]);
        if (lb == 0) { MBAR_WAIT(mb, ph0); }
        else         { MBAR_WAIT(mb, ph1); }
    }
    asm volatile("tcgen05.fence::after_thread_sync;" ::: "memory");

    if (wid < 4) {
        int m = m0 + wid * 32 + lid;
        float alphav = (epi == 1) ? alpha[0] : 0.f;
        float sw_ = 0.f, sbv = 0.f;
        if (epi == 2) { int bidx = m / NN; sw_ = saw[bidx]; sbv = sab[bidx]; }
        #pragma unroll
        for (int c0 = 0; c0 < 128; c0 += 32) {
            uint32_t r[32];
            LDTM_X32(r, tmem + c0);
            asm volatile("tcgen05.wait::ld.sync.aligned;" ::: "memory");
            float* orow = out + (size_t)m * N + n0 + c0;
            const float* rrow = (epi == 1) ? (res + (size_t)m * N + n0 + c0) : nullptr;
            #pragma unroll
            for (int j = 0; j < 32; j++) {
                int n = n0 + c0 + j;
                float v = __uint_as_float(r[j]) + bias[n];
                if (epi == 1) {
                    float y = rrow[j] + v;
                    v = (y - rm[n]) * (gam[n] * rsqrtf(rv[n] + EPSL)) + bet[n] + alphav * y;
                } else if (epi == 2) {
                    float w = sw_ * v + sbv;
                    v = v / (1.f + __expf(-w * v));
                }
                orow[j] = v;
            }
        }
    }
    __syncthreads();
    if (tid == 0) {
        asm volatile("mbarrier.inval.shared.b64 [%0];" :: "r"(smem_u32(&s_mbar[0])) : "memory");
        asm volatile("mbarrier.inval.shared.b64 [%0];" :: "r"(smem_u32(&s_mbar[1])) : "memory");
    }
    __syncthreads();
    if (wid == 0)
        asm volatile("tcgen05.dealloc.cta_group::1.sync.aligned.b32 %0, %1;"
                     :: "r"(tmem), "r"(128));
#endif  // TC_OK
}

// ---------------- attention: one block per (head, batch) ----------------------
__global__ void k_attn(const float* __restrict__ qkv, float* __restrict__ attnout) {
    extern __shared__ float sh[];
    float* Ks = sh;
    float* Vs = sh + NN * 32;
    int h = blockIdx.x, b = blockIdx.y;
    int tid = threadIdx.x;
    size_t base = (size_t)b * NN * 768;
    int koff = 256 + h * 32, voff = 512 + h * 32;
    for (int i = tid; i < NN * 32; i += 256) {
        int m = i >> 5, d = i & 31;
        Ks[i] = qkv[base + (size_t)m * 768 + koff + d];
        Vs[i] = qkv[base + (size_t)m * 768 + voff + d];
    }
    __syncthreads();
    if (tid < NN) {
        float q[32], o[32];
        const float* qp = qkv + base + (size_t)tid * 768 + h * 32;
        #pragma unroll
        for (int d = 0; d < 32; d++) { q[d] = qp[d] * 0.17677669529663687f; o[d] = 0.f; }
        float mx = -1e30f, l = 0.f;
        for (int m = 0; m < NN; m++) {
            const float* kr = Ks + m * 32;
            float s = 0.f;
            #pragma unroll
            for (int d = 0; d < 32; d++) s += q[d] * kr[d];
            float nm = fmaxf(mx, s);
            float f = __expf(mx - nm);
            float p = __expf(s - nm);
            l = l * f + p;
            const float* vr = Vs + m * 32;
            #pragma unroll
            for (int d = 0; d < 32; d++) o[d] = o[d] * f + p * vr[d];
            mx = nm;
        }
        float inv = 1.f / l;
        float* op = attnout + ((size_t)(b * NN + tid)) * CC + h * 32;
        #pragma unroll
        for (int d = 0; d < 32; d++) op[d] = o[d] * inv;
    }
}

// ---------------- launch ------------------------------------------------------
extern "C" void kernel_launch(void* const* d_in, const int* in_sizes, int n_in,
                              void* d_out, int out_size) {
    const float* x      = (const float*)d_in[0];
    const float* W_qkv  = (const float*)d_in[1];
    const float* b_qkv  = (const float*)d_in[2];
    const float* W_proj = (const float*)d_in[3];
    const float* b_proj = (const float*)d_in[4];
    const float* W1     = (const float*)d_in[5];
    const float* b1     = (const float*)d_in[6];
    const float* W2     = (const float*)d_in[7];
    const float* b2     = (const float*)d_in[8];
    const float* sa_w   = (const float*)d_in[9];
    const float* sa_b   = (const float*)d_in[10];
    const float* alpha1 = (const float*)d_in[11];
    const float* gamma1 = (const float*)d_in[12];
    const float* beta1  = (const float*)d_in[13];
    const float* rm1    = (const float*)d_in[14];
    const float* rv1    = (const float*)d_in[15];
    const float* alpha2 = (const float*)d_in[16];
    const float* gamma2 = (const float*)d_in[17];
    const float* beta2  = (const float*)d_in[18];
    const float* rm2    = (const float*)d_in[19];
    const float* rv2    = (const float*)d_in[20];
    float* out = (float*)d_out;

    float *t, *qkv, *attn, *t1, *hbuf, *t2, *wqkvT, *wprojT, *w1T, *w2T;
    cudaGetSymbolAddress((void**)&t,      g_t);
    cudaGetSymbolAddress((void**)&qkv,    g_qkv);
    cudaGetSymbolAddress((void**)&attn,   g_attn);
    cudaGetSymbolAddress((void**)&t1,     g_t1);
    cudaGetSymbolAddress((void**)&hbuf,   g_h);
    cudaGetSymbolAddress((void**)&t2,     g_t2);
    cudaGetSymbolAddress((void**)&wqkvT,  g_wqkvT);
    cudaGetSymbolAddress((void**)&wprojT, g_wprojT);
    cudaGetSymbolAddress((void**)&w1T,    g_w1T);
    cudaGetSymbolAddress((void**)&w2T,    g_w2T);

    const int GEMM_SMEM = 1024 + 4 * 16384;
    cudaFuncSetAttribute(k_tgemm, cudaFuncAttributeMaxDynamicSharedMemorySize, GEMM_SMEM);
    cudaFuncSetAttribute(k_attn, cudaFuncAttributeMaxDynamicSharedMemorySize, 2 * NN * 32 * 4);

    dim3 tb(32, 8);
    // 0) weight transposes  W[K,N] -> Wt[N,K]
    k_wt<<<dim3(768 / 32, 256 / 32), tb>>>(W_qkv, wqkvT, 256, 768);
    k_wt<<<dim3(256 / 32, 256 / 32), tb>>>(W_proj, wprojT, 256, 256);
    k_wt<<<dim3(CMID / 32, 256 / 32), tb>>>(W1, w1T, 256, CMID);
    k_wt<<<dim3(256 / 32, CMID / 32), tb>>>(W2, w2T, CMID, 256);
    // 1) x -> tokens
    k_in_transpose<<<dim3(7, 8, BB), tb>>>(x, t);
    // 2) QKV GEMM [50176,256] @ [256,768]
    k_tgemm<<<dim3(768 / 128, MM / 128), 256, GEMM_SMEM>>>(t, wqkvT, b_qkv, qkv,
        MM, 768, 256, 0, nullptr, nullptr, nullptr, nullptr, nullptr, nullptr, nullptr, nullptr);
    // 3) attention per (h, b)
    k_attn<<<dim3(8, BB), 256, 2 * NN * 32 * 4>>>(qkv, attn);
    // 4) proj + residual + repbn1
    k_tgemm<<<dim3(256 / 128, MM / 128), 256, GEMM_SMEM>>>(attn, wprojT, b_proj, t1,
        MM, 256, 256, 1, t, gamma1, beta1, rm1, rv1, alpha1, nullptr, nullptr);
    // 5) FFN1 + SpatialSILU
    k_tgemm<<<dim3(CMID / 128, MM / 128), 256, GEMM_SMEM>>>(t1, w1T, b1, hbuf,
        MM, CMID, 256, 2, nullptr, nullptr, nullptr, nullptr, nullptr, nullptr, sa_w, sa_b);
    // 6) FFN2 + residual + repbn2
    k_tgemm<<<dim3(256 / 128, MM / 128), 256, GEMM_SMEM>>>(hbuf, w2T, b2, t2,
        MM, 256, CMID, 1, t1, gamma2, beta2, rm2, rv2, alpha2, nullptr, nullptr);
    // 7) tokens -> output layout
    k_out_transpose<<<dim3(8, 7, BB), tb>>>(t2, out);
}

// round 4
// speedup vs baseline: 2.6736x; 1.6376x over previous
#include <cuda_runtime.h>
#include <cstdint>
#include <math.h>

#define BB 256
#define CC 256
#define NN 196
#define MM (BB*NN)        // 50176
#define CMID 2048
#define EPSL 1e-5f

// tcgen05 PTX is only legal in the arch-specific ('a') compilation pass.
#if defined(__CUDA_ARCH_FEAT_SM103_ALL) || defined(__CUDA_ARCH_FEAT_SM100_ALL) || defined(__CUDA_ARCH_FEAT_SM101_ALL)
#define TC_OK 1
#else
#define TC_OK 0
#endif

// ---------------- scratch (device globals) -----------------------------------
__device__ float g_t   [(size_t)MM*CC];
__device__ float g_qkv [(size_t)MM*3*CC];
__device__ float g_attn[(size_t)MM*CC];
__device__ float g_t1  [(size_t)MM*CC];
__device__ float g_h   [(size_t)MM*CMID];
__device__ float g_t2  [(size_t)MM*CC];
__device__ float g_wqkvT[(size_t)3*CC*CC];   // [768,256]
__device__ float g_wprojT[(size_t)CC*CC];    // [256,256]
__device__ float g_w1T  [(size_t)CMID*CC];   // [2048,256]
__device__ float g_w2T  [(size_t)CC*CMID];   // [256,2048]

// ---------------- PTX helpers -------------------------------------------------
__device__ __forceinline__ uint32_t smem_u32(const void* p) {
    uint32_t a;
    asm("{ .reg .u64 t; cvta.to.shared.u64 t, %1; cvt.u32.u64 %0, t; }" : "=r"(a) : "l"(p));
    return a;
}

#define MBAR_INIT(addr, cnt) \
    asm volatile("mbarrier.init.shared.b64 [%0], %1;" :: "r"(addr), "r"(cnt) : "memory")

#define MBAR_WAIT(addr, parity) do {                                              \
    uint32_t _m = (addr); uint32_t _p = (parity); uint32_t _d;                    \
    asm volatile("{\n\t.reg .pred p;\n\t"                                         \
        "mbarrier.try_wait.parity.acquire.cta.shared::cta.b64 p, [%1], %2;\n\t"   \
        "selp.b32 %0, 1, 0, p;\n\t}" : "=r"(_d) : "r"(_m), "r"(_p) : "memory");   \
    if (!_d) {                                                                     \
        asm volatile("{\n\t.reg .pred P1;\n\t"                                     \
            "W_%=:\n\t"                                                            \
            "mbarrier.try_wait.parity.acquire.cta.shared::cta.b64 P1, [%0], %1, 0x989680;\n\t" \
            "@P1 bra.uni D_%=;\n\t"                                                \
            "bra.uni W_%=;\n\t"                                                    \
            "D_%=:\n\t}" :: "r"(_m), "r"(_p) : "memory");                          \
    } } while (0)

#if TC_OK
__device__ __forceinline__ void mma_tf32(uint32_t d, uint64_t ad, uint64_t bd,
                                         uint32_t idesc, bool acc) {
    uint32_t e = acc ? 1u : 0u;
    asm volatile(
        "{\n\t.reg .pred p;\n\tsetp.ne.u32 p, %5, 0;\n\t"
        "tcgen05.mma.cta_group::1.kind::tf32 [%0], %1, %2, %3, {%4, %4, %4, %4}, p;\n\t}"
        :: "r"(d), "l"(ad), "l"(bd), "r"(idesc), "r"(0u), "r"(e) : "memory");
}

#define LDTM_X32(r, addr)                                                         \
    asm volatile("tcgen05.ld.sync.aligned.32x32b.x32.b32 "                        \
        "{%0, %1, %2, %3, %4, %5, %6, %7, %8, %9, %10, %11, %12, %13, %14, %15, " \
        " %16, %17, %18, %19, %20, %21, %22, %23, %24, %25, %26, %27, %28, %29, %30, %31}, [%32];" \
        : "=r"((r)[0]), "=r"((r)[1]), "=r"((r)[2]), "=r"((r)[3]),                 \
          "=r"((r)[4]), "=r"((r)[5]), "=r"((r)[6]), "=r"((r)[7]),                 \
          "=r"((r)[8]), "=r"((r)[9]), "=r"((r)[10]), "=r"((r)[11]),               \
          "=r"((r)[12]), "=r"((r)[13]), "=r"((r)[14]), "=r"((r)[15]),             \
          "=r"((r)[16]), "=r"((r)[17]), "=r"((r)[18]), "=r"((r)[19]),             \
          "=r"((r)[20]), "=r"((r)[21]), "=r"((r)[22]), "=r"((r)[23]),             \
          "=r"((r)[24]), "=r"((r)[25]), "=r"((r)[26]), "=r"((r)[27]),             \
          "=r"((r)[28]), "=r"((r)[29]), "=r"((r)[30]), "=r"((r)[31])              \
        : "r"(addr))
#endif

static constexpr uint64_t DESC_BASE =
    (uint64_t(2) << 61) | (uint64_t(1) << 46) | (uint64_t(64) << 32) | (uint64_t(1) << 16);

// ---------------- transpose x [B][C][N] -> t [B*N][C] -------------------------
__global__ void k_in_transpose(const float* __restrict__ x, float* __restrict__ t) {
    __shared__ float tile[32][33];
    int b = blockIdx.z;
    int n0 = blockIdx.x * 32, c0 = blockIdx.y * 32;
    int tx = threadIdx.x, ty = threadIdx.y;
    const float* xb = x + (size_t)b * CC * NN;
    #pragma unroll
    for (int j = 0; j < 32; j += 8) {
        int c = c0 + ty + j, n = n0 + tx;
        if (n < NN) tile[ty + j][tx] = xb[(size_t)c * NN + n];
    }
    __syncthreads();
    #pragma unroll
    for (int j = 0; j < 32; j += 8) {
        int n = n0 + ty + j, c = c0 + tx;
        if (n < NN) t[((size_t)b * NN + n) * CC + c] = tile[tx][ty + j];
    }
}

// ---------------- transpose t2 [B*N][C] -> out [B][C][N] ----------------------
__global__ void k_out_transpose(const float* __restrict__ t, float* __restrict__ out) {
    __shared__ float tile[32][33];
    int b = blockIdx.z;
    int c0 = blockIdx.x * 32, n0 = blockIdx.y * 32;
    int tx = threadIdx.x, ty = threadIdx.y;
    #pragma unroll
    for (int j = 0; j < 32; j += 8) {
        int n = n0 + ty + j, c = c0 + tx;
        if (n < NN) tile[ty + j][tx] = t[((size_t)b * NN + n) * CC + c];
    }
    __syncthreads();
    #pragma unroll
    for (int j = 0; j < 32; j += 8) {
        int c = c0 + ty + j, n = n0 + tx;
        if (n < NN) out[((size_t)b * CC + c) * NN + n] = tile[tx][ty + j];
    }
}

// ---------------- weight transpose W[R,C] -> Wt[C,R] --------------------------
__global__ void k_wt(const float* __restrict__ W, float* __restrict__ Wt, int R, int C) {
    __shared__ float tile[32][33];
    int c0 = blockIdx.x * 32, r0 = blockIdx.y * 32;
    int tx = threadIdx.x, ty = threadIdx.y;
    #pragma unroll
    for (int j = 0; j < 32; j += 8)
        tile[ty + j][tx] = W[(size_t)(r0 + ty + j) * C + c0 + tx];
    __syncthreads();
    #pragma unroll
    for (int j = 0; j < 32; j += 8)
        Wt[(size_t)(c0 + ty + j) * R + r0 + tx] = tile[tx][ty + j];
}

// ---------------- tcgen05 tf32 GEMM: out[M,N] = A[M,K] @ Bt[N,K]^T + epilogue -
// epi 0: +bias
// epi 1: +bias, y = res + v, repbn(y)
// epi 2: +bias, SpatialSILU
__global__ __launch_bounds__(256)
void k_tgemm(const float* __restrict__ A, const float* __restrict__ Bt,
             const float* __restrict__ bias, float* __restrict__ out,
             int M, int N, int K, int epi,
             const float* __restrict__ res,
             const float* __restrict__ gam, const float* __restrict__ bet,
             const float* __restrict__ rm,  const float* __restrict__ rv,
             const float* __restrict__ alpha,
             const float* __restrict__ saw, const float* __restrict__ sab)
{
#if TC_OK
    extern __shared__ char smem_raw[];
    __shared__ uint64_t s_mbar[2];
    __shared__ uint32_t s_tmem;

    uint32_t sb_raw = smem_u32(smem_raw);
    uint32_t tbase = (sb_raw + 1023u) & ~1023u;      // 1KB-aligned tile base (smem addr)
    char* tptr = smem_raw + (tbase - sb_raw);        // generic ptr to same place

    int tid = threadIdx.x;
    int wid = tid >> 5, lid = tid & 31;
    int m0 = blockIdx.y * 128, n0 = blockIdx.x * 128;

    if (wid == 0)
        asm volatile("tcgen05.alloc.cta_group::1.sync.aligned.shared::cta.b32 [%0], %1;"
                     :: "r"(smem_u32(&s_tmem)), "r"(128) : "memory");
    if (tid == 0) {
        MBAR_INIT(smem_u32(&s_mbar[0]), 1);
        MBAR_INIT(smem_u32(&s_mbar[1]), 1);
    }
    __syncthreads();
    uint32_t tmem = s_tmem;
    if (wid == 0)
        asm volatile("tcgen05.relinquish_alloc_permit.cta_group::1.sync.aligned;");

    // idesc: D=f32, A=tf32, B=tf32, N=128, M=128
    const uint32_t IDESC = (1u << 4) | (2u << 7) | (2u << 10) | (16u << 17) | (8u << 24);
    const int KC = K >> 5;
    int ph0 = 0, ph1 = 0;

    for (int kc = 0; kc < KC; kc++) {
        int buf = kc & 1;
        uint32_t mb = smem_u32(&s_mbar[buf]);
        if (kc >= 2) {
            if (buf == 0) { MBAR_WAIT(mb, ph0); ph0 ^= 1; }
            else          { MBAR_WAIT(mb, ph1); ph1 ^= 1; }
        }
        char* tA = tptr + buf * 32768;
        char* tB = tA + 16384;
        const float* Ag = A + (size_t)m0 * K + kc * 32;
        const float* Bg = Bt + (size_t)n0 * K + kc * 32;
        #pragma unroll
        for (int i = 0; i < 4; i++) {
            int idx = tid + i * 256;
            int row = idx >> 3, c4 = idx & 7;
            float4 av = *(const float4*)(Ag + (size_t)row * K + c4 * 4);
            float4 bv = *(const float4*)(Bg + (size_t)row * K + c4 * 4);
            uint32_t bo = row * 128 + c4 * 16;
            uint32_t sw = bo ^ ((bo >> 3) & 0x70);
            *(float4*)(tA + sw) = av;
            *(float4*)(tB + sw) = bv;
        }
        asm volatile("fence.proxy.async.shared::cta;" ::: "memory");
        __syncthreads();
        if (tid == 0) {
            uint32_t sA = tbase + buf * 32768;
            uint32_t sB = sA + 16384;
            uint64_t ad = DESC_BASE | ((uint64_t)(sA >> 4) & 0x3FFF);
            uint64_t bd = DESC_BASE | ((uint64_t)(sB >> 4) & 0x3FFF);
            #pragma unroll
            for (int s = 0; s < 4; s++)
                mma_tf32(tmem, ad + s * 2, bd + s * 2, IDESC, (kc > 0) || (s > 0));
            asm volatile(
                "tcgen05.commit.cta_group::1.mbarrier::arrive::one.shared::cluster.b64 [%0];"
                :: "r"(mb) : "memory");
        }
    }

    // wait for the last chunk's mma (commit tracks ALL previously issued MMAs)
    {
        int lb = (KC - 1) & 1;
        uint32_t mb = smem_u32(&s_mbar[lb]);
        if (lb == 0) { MBAR_WAIT(mb, ph0); }
        else         { MBAR_WAIT(mb, ph1); }
    }
    asm volatile("tcgen05.fence::after_thread_sync;" ::: "memory");
    __syncthreads();   // all warps past the wait; tile smem now dead -> reuse

    // ---- coalesced epilogue: 32x32 TMEM block -> smem transpose -> float4 IO ----
    if (wid < 4) {
        float* spatch = (float*)tptr + wid * (32 * 33);
        int mrow = m0 + wid * 32;
        float alphav = (epi == 1) ? alpha[0] : 0.f;
        for (int c0 = 0; c0 < 128; c0 += 32) {
            uint32_t r[32];
            LDTM_X32(r, tmem + c0);
            asm volatile("tcgen05.wait::ld.sync.aligned;" ::: "memory");
            #pragma unroll
            for (int j = 0; j < 32; j++) spatch[lid * 33 + j] = __uint_as_float(r[j]);
            __syncwarp();
            #pragma unroll
            for (int i = 0; i < 8; i++) {
                int rr = i * 4 + (lid >> 3);          // row within warp patch
                int c4 = (lid & 7) * 4;               // col (float4 granularity)
                int m = mrow + rr;
                int n = n0 + c0 + c4;
                float vv[4];
                #pragma unroll
                for (int e = 0; e < 4; e++) vv[e] = spatch[rr * 33 + c4 + e];
                float4 bb = *(const float4*)(bias + n);
                vv[0] += bb.x; vv[1] += bb.y; vv[2] += bb.z; vv[3] += bb.w;
                if (epi == 1) {
                    float4 r4 = *(const float4*)(res + (size_t)m * N + n);
                    float4 g4 = *(const float4*)(gam + n);
                    float4 b4 = *(const float4*)(bet + n);
                    float4 u4 = *(const float4*)(rm + n);
                    float4 s4 = *(const float4*)(rv + n);
                    float y;
                    y = r4.x + vv[0]; vv[0] = (y - u4.x) * (g4.x * rsqrtf(s4.x + EPSL)) + b4.x + alphav * y;
                    y = r4.y + vv[1]; vv[1] = (y - u4.y) * (g4.y * rsqrtf(s4.y + EPSL)) + b4.y + alphav * y;
                    y = r4.z + vv[2]; vv[2] = (y - u4.z) * (g4.z * rsqrtf(s4.z + EPSL)) + b4.z + alphav * y;
                    y = r4.w + vv[3]; vv[3] = (y - u4.w) * (g4.w * rsqrtf(s4.w + EPSL)) + b4.w + alphav * y;
                } else if (epi == 2) {
                    int bidx = m / NN;
                    float sw_ = saw[bidx], sbv = sab[bidx];
                    #pragma unroll
                    for (int e = 0; e < 4; e++) {
                        float w = sw_ * vv[e] + sbv;
                        vv[e] = vv[e] / (1.f + __expf(-w * vv[e]));
                    }
                }
                float4 o4 = make_float4(vv[0], vv[1], vv[2], vv[3]);
                *(float4*)(out + (size_t)m * N + n) = o4;
            }
            __syncwarp();
        }
    }
    __syncthreads();
    if (tid == 0) {
        asm volatile("mbarrier.inval.shared.b64 [%0];" :: "r"(smem_u32(&s_mbar[0])) : "memory");
        asm volatile("mbarrier.inval.shared.b64 [%0];" :: "r"(smem_u32(&s_mbar[1])) : "memory");
    }
    __syncthreads();
    if (wid == 0)
        asm volatile("tcgen05.dealloc.cta_group::1.sync.aligned.b32 %0, %1;"
                     :: "r"(tmem), "r"(128));
#endif  // TC_OK
}

// ---------------- attention: one block per (head, batch) ----------------------
__global__ void k_attn(const float* __restrict__ qkv, float* __restrict__ attnout) {
    extern __shared__ float sh[];
    float* Ks = sh;
    float* Vs = sh + NN * 32;
    int h = blockIdx.x, b = blockIdx.y;
    int tid = threadIdx.x;
    size_t base = (size_t)b * NN * 768;
    int koff = 256 + h * 32, voff = 512 + h * 32;
    for (int i = tid; i < NN * 32; i += 256) {
        int m = i >> 5, d = i & 31;
        Ks[i] = qkv[base + (size_t)m * 768 + koff + d];
        Vs[i] = qkv[base + (size_t)m * 768 + voff + d];
    }
    __syncthreads();
    if (tid < NN) {
        float q[32], o[32];
        const float* qp = qkv + base + (size_t)tid * 768 + h * 32;
        #pragma unroll
        for (int d = 0; d < 32; d++) { q[d] = qp[d] * 0.17677669529663687f; o[d] = 0.f; }
        float mx = -1e30f, l = 0.f;
        for (int m = 0; m < NN; m++) {
            const float* kr = Ks + m * 32;
            float s = 0.f;
            #pragma unroll
            for (int d = 0; d < 32; d++) s += q[d] * kr[d];
            float nm = fmaxf(mx, s);
            float f = __expf(mx - nm);
            float p = __expf(s - nm);
            l = l * f + p;
            const float* vr = Vs + m * 32;
            #pragma unroll
            for (int d = 0; d < 32; d++) o[d] = o[d] * f + p * vr[d];
            mx = nm;
        }
        float inv = 1.f / l;
        float* op = attnout + ((size_t)(b * NN + tid)) * CC + h * 32;
        #pragma unroll
        for (int d = 0; d < 32; d++) op[d] = o[d] * inv;
    }
}

// ---------------- launch ------------------------------------------------------
extern "C" void kernel_launch(void* const* d_in, const int* in_sizes, int n_in,
                              void* d_out, int out_size) {
    const float* x      = (const float*)d_in[0];
    const float* W_qkv  = (const float*)d_in[1];
    const float* b_qkv  = (const float*)d_in[2];
    const float* W_proj = (const float*)d_in[3];
    const float* b_proj = (const float*)d_in[4];
    const float* W1     = (const float*)d_in[5];
    const float* b1     = (const float*)d_in[6];
    const float* W2     = (const float*)d_in[7];
    const float* b2     = (const float*)d_in[8];
    const float* sa_w   = (const float*)d_in[9];
    const float* sa_b   = (const float*)d_in[10];
    const float* alpha1 = (const float*)d_in[11];
    const float* gamma1 = (const float*)d_in[12];
    const float* beta1  = (const float*)d_in[13];
    const float* rm1    = (const float*)d_in[14];
    const float* rv1    = (const float*)d_in[15];
    const float* alpha2 = (const float*)d_in[16];
    const float* gamma2 = (const float*)d_in[17];
    const float* beta2  = (const float*)d_in[18];
    const float* rm2    = (const float*)d_in[19];
    const float* rv2    = (const float*)d_in[20];
    float* out = (float*)d_out;

    float *t, *qkv, *attn, *t1, *hbuf, *t2, *wqkvT, *wprojT, *w1T, *w2T;
    cudaGetSymbolAddress((void**)&t,      g_t);
    cudaGetSymbolAddress((void**)&qkv,    g_qkv);
    cudaGetSymbolAddress((void**)&attn,   g_attn);
    cudaGetSymbolAddress((void**)&t1,     g_t1);
    cudaGetSymbolAddress((void**)&hbuf,   g_h);
    cudaGetSymbolAddress((void**)&t2,     g_t2);
    cudaGetSymbolAddress((void**)&wqkvT,  g_wqkvT);
    cudaGetSymbolAddress((void**)&wprojT, g_wprojT);
    cudaGetSymbolAddress((void**)&w1T,    g_w1T);
    cudaGetSymbolAddress((void**)&w2T,    g_w2T);

    const int GEMM_SMEM = 1024 + 4 * 16384;
    cudaFuncSetAttribute(k_tgemm, cudaFuncAttributeMaxDynamicSharedMemorySize, GEMM_SMEM);
    cudaFuncSetAttribute(k_attn, cudaFuncAttributeMaxDynamicSharedMemorySize, 2 * NN * 32 * 4);

    dim3 tb(32, 8);
    // 0) weight transposes  W[K,N] -> Wt[N,K]
    k_wt<<<dim3(768 / 32, 256 / 32), tb>>>(W_qkv, wqkvT, 256, 768);
    k_wt<<<dim3(256 / 32, 256 / 32), tb>>>(W_proj, wprojT, 256, 256);
    k_wt<<<dim3(CMID / 32, 256 / 32), tb>>>(W1, w1T, 256, CMID);
    k_wt<<<dim3(256 / 32, CMID / 32), tb>>>(W2, w2T, CMID, 256);
    // 1) x -> tokens
    k_in_transpose<<<dim3(7, 8, BB), tb>>>(x, t);
    // 2) QKV GEMM [50176,256] @ [256,768]
    k_tgemm<<<dim3(768 / 128, MM / 128), 256, GEMM_SMEM>>>(t, wqkvT, b_qkv, qkv,
        MM, 768, 256, 0, nullptr, nullptr, nullptr, nullptr, nullptr, nullptr, nullptr, nullptr);
    // 3) attention per (h, b)
    k_attn<<<dim3(8, BB), 256, 2 * NN * 32 * 4>>>(qkv, attn);
    // 4) proj + residual + repbn1
    k_tgemm<<<dim3(256 / 128, MM / 128), 256, GEMM_SMEM>>>(attn, wprojT, b_proj, t1,
        MM, 256, 256, 1, t, gamma1, beta1, rm1, rv1, alpha1, nullptr, nullptr);
    // 5) FFN1 + SpatialSILU
    k_tgemm<<<dim3(CMID / 128, MM / 128), 256, GEMM_SMEM>>>(t1, w1T, b1, hbuf,
        MM, CMID, 256, 2, nullptr, nullptr, nullptr, nullptr, nullptr, nullptr, sa_w, sa_b);
    // 6) FFN2 + residual + repbn2
    k_tgemm<<<dim3(256 / 128, MM / 128), 256, GEMM_SMEM>>>(hbuf, w2T, b2, t2,
        MM, 256, CMID, 1, t1, gamma2, beta2, rm2, rv2, alpha2, nullptr, nullptr);
    // 7) tokens -> output layout
    k_out_transpose<<<dim3(8, 7, BB), tb>>>(t2, out);
}

// round 5
// speedup vs baseline: 2.9223x; 1.0930x over previous
#include <cuda_runtime.h>
#include <cstdint>
#include <math.h>

#define BB 256
#define CC 256
#define NN 196
#define MM (BB*NN)        // 50176
#define CMID 2048
#define EPSL 1e-5f

// tcgen05 PTX is only legal in the arch-specific ('a') compilation pass.
#if defined(__CUDA_ARCH_FEAT_SM103_ALL) || defined(__CUDA_ARCH_FEAT_SM100_ALL) || defined(__CUDA_ARCH_FEAT_SM101_ALL)
#define TC_OK 1
#else
#define TC_OK 0
#endif

// ---------------- scratch (device globals) -----------------------------------
__device__ float g_t   [(size_t)MM*CC];
__device__ float g_qkv [(size_t)MM*3*CC];
__device__ float g_attn[(size_t)MM*CC];
__device__ float g_t1  [(size_t)MM*CC];
__device__ float g_h   [(size_t)MM*CMID];
__device__ float g_t2  [(size_t)MM*CC];
__device__ float g_wqkvT[(size_t)3*CC*CC];   // [768,256]
__device__ float g_wprojT[(size_t)CC*CC];    // [256,256]
__device__ float g_w1T  [(size_t)CMID*CC];   // [2048,256]
__device__ float g_w2T  [(size_t)CC*CMID];   // [256,2048]

// ---------------- PTX helpers -------------------------------------------------
__device__ __forceinline__ uint32_t smem_u32(const void* p) {
    uint32_t a;
    asm("{ .reg .u64 t; cvta.to.shared.u64 t, %1; cvt.u32.u64 %0, t; }" : "=r"(a) : "l"(p));
    return a;
}

#define MBAR_INIT(addr, cnt) \
    asm volatile("mbarrier.init.shared.b64 [%0], %1;" :: "r"(addr), "r"(cnt) : "memory")

#define MBAR_WAIT(addr, parity) do {                                              \
    uint32_t _m = (addr); uint32_t _p = (parity); uint32_t _d;                    \
    asm volatile("{\n\t.reg .pred p;\n\t"                                         \
        "mbarrier.try_wait.parity.acquire.cta.shared::cta.b64 p, [%1], %2;\n\t"   \
        "selp.b32 %0, 1, 0, p;\n\t}" : "=r"(_d) : "r"(_m), "r"(_p) : "memory");   \
    if (!_d) {                                                                     \
        asm volatile("{\n\t.reg .pred P1;\n\t"                                     \
            "W_%=:\n\t"                                                            \
            "mbarrier.try_wait.parity.acquire.cta.shared::cta.b64 P1, [%0], %1, 0x989680;\n\t" \
            "@P1 bra.uni D_%=;\n\t"                                                \
            "bra.uni W_%=;\n\t"                                                    \
            "D_%=:\n\t}" :: "r"(_m), "r"(_p) : "memory");                          \
    } } while (0)

#if TC_OK
__device__ __forceinline__ void mma_tf32(uint32_t d, uint64_t ad, uint64_t bd,
                                         uint32_t idesc, bool acc) {
    uint32_t e = acc ? 1u : 0u;
    asm volatile(
        "{\n\t.reg .pred p;\n\tsetp.ne.u32 p, %5, 0;\n\t"
        "tcgen05.mma.cta_group::1.kind::tf32 [%0], %1, %2, %3, {%4, %4, %4, %4}, p;\n\t}"
        :: "r"(d), "l"(ad), "l"(bd), "r"(idesc), "r"(0u), "r"(e) : "memory");
}

#define LDTM_X32(r, addr)                                                         \
    asm volatile("tcgen05.ld.sync.aligned.32x32b.x32.b32 "                        \
        "{%0, %1, %2, %3, %4, %5, %6, %7, %8, %9, %10, %11, %12, %13, %14, %15, " \
        " %16, %17, %18, %19, %20, %21, %22, %23, %24, %25, %26, %27, %28, %29, %30, %31}, [%32];" \
        : "=r"((r)[0]), "=r"((r)[1]), "=r"((r)[2]), "=r"((r)[3]),                 \
          "=r"((r)[4]), "=r"((r)[5]), "=r"((r)[6]), "=r"((r)[7]),                 \
          "=r"((r)[8]), "=r"((r)[9]), "=r"((r)[10]), "=r"((r)[11]),               \
          "=r"((r)[12]), "=r"((r)[13]), "=r"((r)[14]), "=r"((r)[15]),             \
          "=r"((r)[16]), "=r"((r)[17]), "=r"((r)[18]), "=r"((r)[19]),             \
          "=r"((r)[20]), "=r"((r)[21]), "=r"((r)[22]), "=r"((r)[23]),             \
          "=r"((r)[24]), "=r"((r)[25]), "=r"((r)[26]), "=r"((r)[27]),             \
          "=r"((r)[28]), "=r"((r)[29]), "=r"((r)[30]), "=r"((r)[31])              \
        : "r"(addr))
#endif

static constexpr uint64_t DESC_BASE =
    (uint64_t(2) << 61) | (uint64_t(1) << 46) | (uint64_t(64) << 32) | (uint64_t(1) << 16);

// ---------------- transpose x [B][C][N] -> t [B*N][C] -------------------------
__global__ void k_in_transpose(const float* __restrict__ x, float* __restrict__ t) {
    __shared__ float tile[32][33];
    int b = blockIdx.z;
    int n0 = blockIdx.x * 32, c0 = blockIdx.y * 32;
    int tx = threadIdx.x, ty = threadIdx.y;
    const float* xb = x + (size_t)b * CC * NN;
    #pragma unroll
    for (int j = 0; j < 32; j += 8) {
        int c = c0 + ty + j, n = n0 + tx;
        if (n < NN) tile[ty + j][tx] = xb[(size_t)c * NN + n];
    }
    __syncthreads();
    #pragma unroll
    for (int j = 0; j < 32; j += 8) {
        int n = n0 + ty + j, c = c0 + tx;
        if (n < NN) t[((size_t)b * NN + n) * CC + c] = tile[tx][ty + j];
    }
}

// ---------------- transpose t2 [B*N][C] -> out [B][C][N] ----------------------
__global__ void k_out_transpose(const float* __restrict__ t, float* __restrict__ out) {
    __shared__ float tile[32][33];
    int b = blockIdx.z;
    int c0 = blockIdx.x * 32, n0 = blockIdx.y * 32;
    int tx = threadIdx.x, ty = threadIdx.y;
    #pragma unroll
    for (int j = 0; j < 32; j += 8) {
        int n = n0 + ty + j, c = c0 + tx;
        if (n < NN) tile[ty + j][tx] = t[((size_t)b * NN + n) * CC + c];
    }
    __syncthreads();
    #pragma unroll
    for (int j = 0; j < 32; j += 8) {
        int c = c0 + ty + j, n = n0 + tx;
        if (n < NN) out[((size_t)b * CC + c) * NN + n] = tile[tx][ty + j];
    }
}

// ---------------- weight transpose W[R,C] -> Wt[C,R] --------------------------
__global__ void k_wt(const float* __restrict__ W, float* __restrict__ Wt, int R, int C) {
    __shared__ float tile[32][33];
    int c0 = blockIdx.x * 32, r0 = blockIdx.y * 32;
    int tx = threadIdx.x, ty = threadIdx.y;
    #pragma unroll
    for (int j = 0; j < 32; j += 8)
        tile[ty + j][tx] = W[(size_t)(r0 + ty + j) * C + c0 + tx];
    __syncthreads();
    #pragma unroll
    for (int j = 0; j < 32; j += 8)
        Wt[(size_t)(c0 + ty + j) * R + r0 + tx] = tile[tx][ty + j];
}

// ---------------- tcgen05 tf32 GEMM: out[M,N] = A[M,K] @ Bt[N,K]^T + epilogue -
// epi 0: +bias
// epi 1: +bias, y = res + v, repbn(y)
// epi 2: +bias, SpatialSILU
__global__ __launch_bounds__(256)
void k_tgemm(const float* __restrict__ A, const float* __restrict__ Bt,
             const float* __restrict__ bias, float* __restrict__ out,
             int M, int N, int K, int epi,
             const float* __restrict__ res,
             const float* __restrict__ gam, const float* __restrict__ bet,
             const float* __restrict__ rm,  const float* __restrict__ rv,
             const float* __restrict__ alpha,
             const float* __restrict__ saw, const float* __restrict__ sab)
{
#if TC_OK
    extern __shared__ char smem_raw[];
    __shared__ uint64_t s_mbar[2];
    __shared__ uint32_t s_tmem;

    uint32_t sb_raw = smem_u32(smem_raw);
    uint32_t tbase = (sb_raw + 1023u) & ~1023u;      // 1KB-aligned tile base (smem addr)
    char* tptr = smem_raw + (tbase - sb_raw);        // generic ptr to same place

    int tid = threadIdx.x;
    int wid = tid >> 5, lid = tid & 31;
    int m0 = blockIdx.y * 128, n0 = blockIdx.x * 128;

    if (wid == 0)
        asm volatile("tcgen05.alloc.cta_group::1.sync.aligned.shared::cta.b32 [%0], %1;"
                     :: "r"(smem_u32(&s_tmem)), "r"(128) : "memory");
    if (tid == 0) {
        MBAR_INIT(smem_u32(&s_mbar[0]), 1);
        MBAR_INIT(smem_u32(&s_mbar[1]), 1);
    }
    __syncthreads();
    uint32_t tmem = s_tmem;
    if (wid == 0)
        asm volatile("tcgen05.relinquish_alloc_permit.cta_group::1.sync.aligned;");

    // idesc: D=f32, A=tf32, B=tf32, N=128, M=128
    const uint32_t IDESC = (1u << 4) | (2u << 7) | (2u << 10) | (16u << 17) | (8u << 24);
    const int KC = K >> 5;
    int ph0 = 0, ph1 = 0;

    // per-thread tile coordinates (4 rows apart in m/n, 32-float K rows)
    int row_ = tid >> 3, c4_ = tid & 7;
    uint32_t bo0 = row_ * 128 + c4_ * 16;
    uint32_t sw0 = bo0 ^ ((bo0 >> 3) & 0x70);

    // register prefetch of chunk 0
    float4 avr[4], bvr[4];
    {
        const float* Ag = A + (size_t)m0 * K;
        const float* Bg = Bt + (size_t)n0 * K;
        #pragma unroll
        for (int i = 0; i < 4; i++) {
            int row = row_ + i * 32;
            avr[i] = *(const float4*)(Ag + (size_t)row * K + c4_ * 4);
            bvr[i] = *(const float4*)(Bg + (size_t)row * K + c4_ * 4);
        }
    }

    for (int kc = 0; kc < KC; kc++) {
        int buf = kc & 1;
        uint32_t mb = smem_u32(&s_mbar[buf]);
        if (kc >= 2) {
            if (buf == 0) { MBAR_WAIT(mb, ph0); ph0 ^= 1; }
            else          { MBAR_WAIT(mb, ph1); ph1 ^= 1; }
        }
        char* tA = tptr + buf * 32768;
        char* tB = tA + 16384;
        #pragma unroll
        for (int i = 0; i < 4; i++) {
            uint32_t sw = sw0 + i * 4096;   // +32 rows = +4096B, swizzle bits unaffected
            *(float4*)(tA + sw) = avr[i];
            *(float4*)(tB + sw) = bvr[i];
        }
        asm volatile("fence.proxy.async.shared::cta;" ::: "memory");
        __syncthreads();
        if (tid == 0) {
            uint32_t sA = tbase + buf * 32768;
            uint32_t sB = sA + 16384;
            uint64_t ad = DESC_BASE | ((uint64_t)(sA >> 4) & 0x3FFF);
            uint64_t bd = DESC_BASE | ((uint64_t)(sB >> 4) & 0x3FFF);
            #pragma unroll
            for (int s = 0; s < 4; s++)
                mma_tf32(tmem, ad + s * 2, bd + s * 2, IDESC, (kc > 0) || (s > 0));
            asm volatile(
                "tcgen05.commit.cta_group::1.mbarrier::arrive::one.shared::cluster.b64 [%0];"
                :: "r"(mb) : "memory");
        }
        // prefetch next chunk into registers (overlaps MMA + barrier of next iter)
        if (kc + 1 < KC) {
            const float* Ag = A + (size_t)m0 * K + (kc + 1) * 32;
            const float* Bg = Bt + (size_t)n0 * K + (kc + 1) * 32;
            #pragma unroll
            for (int i = 0; i < 4; i++) {
                int row = row_ + i * 32;
                avr[i] = *(const float4*)(Ag + (size_t)row * K + c4_ * 4);
                bvr[i] = *(const float4*)(Bg + (size_t)row * K + c4_ * 4);
            }
        }
    }

    // wait for the last chunk's mma (commit tracks ALL previously issued MMAs)
    {
        int lb = (KC - 1) & 1;
        uint32_t mb = smem_u32(&s_mbar[lb]);
        if (lb == 0) { MBAR_WAIT(mb, ph0); }
        else         { MBAR_WAIT(mb, ph1); }
    }
    asm volatile("tcgen05.fence::after_thread_sync;" ::: "memory");
    __syncthreads();   // all warps past the wait; tile smem now dead -> reuse

    // ---- coalesced epilogue: 32x32 TMEM block -> smem transpose -> float4 IO ----
    if (wid < 4) {
        float* spatch = (float*)tptr + wid * (32 * 33);
        int mrow = m0 + wid * 32;
        float alphav = (epi == 1) ? alpha[0] : 0.f;
        for (int c0 = 0; c0 < 128; c0 += 32) {
            uint32_t r[32];
            LDTM_X32(r, tmem + c0);
            asm volatile("tcgen05.wait::ld.sync.aligned;" ::: "memory");
            #pragma unroll
            for (int j = 0; j < 32; j++) spatch[lid * 33 + j] = __uint_as_float(r[j]);
            __syncwarp();
            #pragma unroll
            for (int i = 0; i < 8; i++) {
                int rr = i * 4 + (lid >> 3);          // row within warp patch
                int c4 = (lid & 7) * 4;               // col (float4 granularity)
                int m = mrow + rr;
                int n = n0 + c0 + c4;
                float vv[4];
                #pragma unroll
                for (int e = 0; e < 4; e++) vv[e] = spatch[rr * 33 + c4 + e];
                float4 bb = *(const float4*)(bias + n);
                vv[0] += bb.x; vv[1] += bb.y; vv[2] += bb.z; vv[3] += bb.w;
                if (epi == 1) {
                    float4 r4 = *(const float4*)(res + (size_t)m * N + n);
                    float4 g4 = *(const float4*)(gam + n);
                    float4 b4 = *(const float4*)(bet + n);
                    float4 u4 = *(const float4*)(rm + n);
                    float4 s4 = *(const float4*)(rv + n);
                    float y;
                    y = r4.x + vv[0]; vv[0] = (y - u4.x) * (g4.x * rsqrtf(s4.x + EPSL)) + b4.x + alphav * y;
                    y = r4.y + vv[1]; vv[1] = (y - u4.y) * (g4.y * rsqrtf(s4.y + EPSL)) + b4.y + alphav * y;
                    y = r4.z + vv[2]; vv[2] = (y - u4.z) * (g4.z * rsqrtf(s4.z + EPSL)) + b4.z + alphav * y;
                    y = r4.w + vv[3]; vv[3] = (y - u4.w) * (g4.w * rsqrtf(s4.w + EPSL)) + b4.w + alphav * y;
                } else if (epi == 2) {
                    int bidx = m / NN;
                    float sw_ = saw[bidx], sbv = sab[bidx];
                    #pragma unroll
                    for (int e = 0; e < 4; e++) {
                        float w = sw_ * vv[e] + sbv;
                        vv[e] = vv[e] / (1.f + __expf(-w * vv[e]));
                    }
                }
                float4 o4 = make_float4(vv[0], vv[1], vv[2], vv[3]);
                *(float4*)(out + (size_t)m * N + n) = o4;
            }
            __syncwarp();
        }
    }
    __syncthreads();
    if (tid == 0) {
        asm volatile("mbarrier.inval.shared.b64 [%0];" :: "r"(smem_u32(&s_mbar[0])) : "memory");
        asm volatile("mbarrier.inval.shared.b64 [%0];" :: "r"(smem_u32(&s_mbar[1])) : "memory");
    }
    __syncthreads();
    if (wid == 0)
        asm volatile("tcgen05.dealloc.cta_group::1.sync.aligned.b32 %0, %1;"
                     :: "r"(tmem), "r"(128));
#endif  // TC_OK
}

// ---------------- attention: one block per (head, batch), float4 + 2-key steps -
__global__ void k_attn(const float* __restrict__ qkv, float* __restrict__ attnout) {
    extern __shared__ float sh[];
    float4* Ks = (float4*)sh;              // [196][8]
    float4* Vs = (float4*)(sh + NN * 32);  // [196][8]
    int h = blockIdx.x, b = blockIdx.y;
    int tid = threadIdx.x;
    size_t base = (size_t)b * NN * 768;
    int koff = 256 + h * 32, voff = 512 + h * 32;
    for (int i = tid; i < NN * 8; i += 256) {
        int m = i >> 3, d = i & 7;
        Ks[i] = *(const float4*)(qkv + base + (size_t)m * 768 + koff + d * 4);
        Vs[i] = *(const float4*)(qkv + base + (size_t)m * 768 + voff + d * 4);
    }
    __syncthreads();
    if (tid < NN) {
        float4 q4[8], o4[8];
        const float* qp = qkv + base + (size_t)tid * 768 + h * 32;
        #pragma unroll
        for (int i = 0; i < 8; i++) {
            float4 qv = *(const float4*)(qp + i * 4);
            const float sc = 0.17677669529663687f;
            q4[i] = make_float4(qv.x * sc, qv.y * sc, qv.z * sc, qv.w * sc);
            o4[i] = make_float4(0.f, 0.f, 0.f, 0.f);
        }
        float mx = -1e30f, l = 0.f;
        for (int m = 0; m < NN; m += 2) {
            const float4* k0 = Ks + m * 8;
            const float4* k1 = k0 + 8;
            float s0 = 0.f, s1 = 0.f;
            #pragma unroll
            for (int i = 0; i < 8; i++) {
                float4 a = q4[i], x0 = k0[i], x1 = k1[i];
                s0 += a.x * x0.x + a.y * x0.y + a.z * x0.z + a.w * x0.w;
                s1 += a.x * x1.x + a.y * x1.y + a.z * x1.z + a.w * x1.w;
            }
            float nm = fmaxf(mx, fmaxf(s0, s1));
            float f  = __expf(mx - nm);
            float p0 = __expf(s0 - nm);
            float p1 = __expf(s1 - nm);
            l = l * f + p0 + p1;
            const float4* v0 = Vs + m * 8;
            const float4* v1 = v0 + 8;
            #pragma unroll
            for (int i = 0; i < 8; i++) {
                float4 o = o4[i], a = v0[i], c = v1[i];
                o.x = o.x * f + p0 * a.x + p1 * c.x;
                o.y = o.y * f + p0 * a.y + p1 * c.y;
                o.z = o.z * f + p0 * a.z + p1 * c.z;
                o.w = o.w * f + p0 * a.w + p1 * c.w;
                o4[i] = o;
            }
            mx = nm;
        }
        float inv = 1.f / l;
        float* op = attnout + ((size_t)(b * NN + tid)) * CC + h * 32;
        #pragma unroll
        for (int i = 0; i < 8; i++) {
            float4 o = o4[i];
            *(float4*)(op + i * 4) = make_float4(o.x * inv, o.y * inv, o.z * inv, o.w * inv);
        }
    }
}

// ---------------- launch ------------------------------------------------------
extern "C" void kernel_launch(void* const* d_in, const int* in_sizes, int n_in,
                              void* d_out, int out_size) {
    const float* x      = (const float*)d_in[0];
    const float* W_qkv  = (const float*)d_in[1];
    const float* b_qkv  = (const float*)d_in[2];
    const float* W_proj = (const float*)d_in[3];
    const float* b_proj = (const float*)d_in[4];
    const float* W1     = (const float*)d_in[5];
    const float* b1     = (const float*)d_in[6];
    const float* W2     = (const float*)d_in[7];
    const float* b2     = (const float*)d_in[8];
    const float* sa_w   = (const float*)d_in[9];
    const float* sa_b   = (const float*)d_in[10];
    const float* alpha1 = (const float*)d_in[11];
    const float* gamma1 = (const float*)d_in[12];
    const float* beta1  = (const float*)d_in[13];
    const float* rm1    = (const float*)d_in[14];
    const float* rv1    = (const float*)d_in[15];
    const float* alpha2 = (const float*)d_in[16];
    const float* gamma2 = (const float*)d_in[17];
    const float* beta2  = (const float*)d_in[18];
    const float* rm2    = (const float*)d_in[19];
    const float* rv2    = (const float*)d_in[20];
    float* out = (float*)d_out;

    float *t, *qkv, *attn, *t1, *hbuf, *t2, *wqkvT, *wprojT, *w1T, *w2T;
    cudaGetSymbolAddress((void**)&t,      g_t);
    cudaGetSymbolAddress((void**)&qkv,    g_qkv);
    cudaGetSymbolAddress((void**)&attn,   g_attn);
    cudaGetSymbolAddress((void**)&t1,     g_t1);
    cudaGetSymbolAddress((void**)&hbuf,   g_h);
    cudaGetSymbolAddress((void**)&t2,     g_t2);
    cudaGetSymbolAddress((void**)&wqkvT,  g_wqkvT);
    cudaGetSymbolAddress((void**)&wprojT, g_wprojT);
    cudaGetSymbolAddress((void**)&w1T,    g_w1T);
    cudaGetSymbolAddress((void**)&w2T,    g_w2T);

    const int GEMM_SMEM = 1024 + 4 * 16384;
    cudaFuncSetAttribute(k_tgemm, cudaFuncAttributeMaxDynamicSharedMemorySize, GEMM_SMEM);
    cudaFuncSetAttribute(k_attn, cudaFuncAttributeMaxDynamicSharedMemorySize, 2 * NN * 32 * 4);

    dim3 tb(32, 8);
    // 0) weight transposes  W[K,N] -> Wt[N,K]
    k_wt<<<dim3(768 / 32, 256 / 32), tb>>>(W_qkv, wqkvT, 256, 768);
    k_wt<<<dim3(256 / 32, 256 / 32), tb>>>(W_proj, wprojT, 256, 256);
    k_wt<<<dim3(CMID / 32, 256 / 32), tb>>>(W1, w1T, 256, CMID);
    k_wt<<<dim3(256 / 32, CMID / 32), tb>>>(W2, w2T, CMID, 256);
    // 1) x -> tokens
    k_in_transpose<<<dim3(7, 8, BB), tb>>>(x, t);
    // 2) QKV GEMM [50176,256] @ [256,768]
    k_tgemm<<<dim3(768 / 128, MM / 128), 256, GEMM_SMEM>>>(t, wqkvT, b_qkv, qkv,
        MM, 768, 256, 0, nullptr, nullptr, nullptr, nullptr, nullptr, nullptr, nullptr, nullptr);
    // 3) attention per (h, b)
    k_attn<<<dim3(8, BB), 256, 2 * NN * 32 * 4>>>(qkv, attn);
    // 4) proj + residual + repbn1
    k_tgemm<<<dim3(256 / 128, MM / 128), 256, GEMM_SMEM>>>(attn, wprojT, b_proj, t1,
        MM, 256, 256, 1, t, gamma1, beta1, rm1, rv1, alpha1, nullptr, nullptr);
    // 5) FFN1 + SpatialSILU
    k_tgemm<<<dim3(CMID / 128, MM / 128), 256, GEMM_SMEM>>>(t1, w1T, b1, hbuf,
        MM, CMID, 256, 2, nullptr, nullptr, nullptr, nullptr, nullptr, nullptr, sa_w, sa_b);
    // 6) FFN2 + residual + repbn2
    k_tgemm<<<dim3(256 / 128, MM / 128), 256, GEMM_SMEM>>>(hbuf, w2T, b2, t2,
        MM, 256, CMID, 1, t1, gamma2, beta2, rm2, rv2, alpha2, nullptr, nullptr);
    // 7) tokens -> output layout
    k_out_transpose<<<dim3(8, 7, BB), tb>>>(t2, out);
}